// round 4
// baseline (speedup 1.0000x reference)
#include <cuda_runtime.h>
#include <cstdint>

// TaylorExp flat-output formulation.
// out is treated as a flat array of n_out = rows*273 floats.
// Thread t computes elements [4t, 4t+4) and writes one aligned STG.128.
// For element g: row = g/273, idx = g%273.
//   idx == 0       -> 1.0
//   1 <= idx <= 16 -> x[row*16 + idx-1] * 0.5
//   idx >= 17      -> k = idx-17; x[row*16 + (k>>4)] * x[row*16 + (k&15)] * s_quad

#define D 16
#define OPR 273
#define THREADS 256

__global__ __launch_bounds__(THREADS)
void taylor_flat_kernel(const float* __restrict__ x,
                        float* __restrict__ out,
                        unsigned int n_out)
{
    const unsigned int g0 =
        ((unsigned int)blockIdx.x * THREADS + threadIdx.x) * 4u;
    if (g0 >= n_out) return;

    unsigned int row = g0 / OPR;              // one constant-division per thread
    int idx = (int)(g0 - row * OPR);
    const float* __restrict__ xr = x + (size_t)row * D;

    const float s_lin  = 0.5f;                 // 1/sqrt(sqrt(16))
    const float s_quad = 0.17677669529663689f; // 1/(sqrt(2)*sqrt(16))

    float v[4];
    #pragma unroll
    for (int e = 0; e < 4; ++e) {
        const int k = idx - 17;
        float val;
        if (k >= 0) {
            // quadratic region (94% of elements); loads predicated on k>=0
            val = xr[k >> 4] * xr[k & 15] * s_quad;
        } else if (idx == 0) {
            val = 1.0f;
        } else {
            val = xr[idx - 1] * s_lin;
        }
        v[e] = val;
        ++idx;
        if (idx == OPR) { idx = 0; xr += D; }   // row crossing (<=1 per thread)
    }

    if (g0 + 3u < n_out) {
        *reinterpret_cast<float4*>(out + g0) = make_float4(v[0], v[1], v[2], v[3]);
    } else {
        #pragma unroll
        for (int e = 0; e < 4; ++e)
            if (g0 + (unsigned)e < n_out) out[g0 + e] = v[e];
    }
}

extern "C" void kernel_launch(void* const* d_in, const int* in_sizes, int n_in,
                              void* d_out, int out_size) {
    const float* x = (const float*)d_in[0];
    float* out = (float*)d_out;

    const unsigned int rows  = (unsigned int)(in_sizes[0] / D);
    const unsigned int n_out = rows * OPR;     // == out_size

    const unsigned int threads_needed = (n_out + 3u) / 4u;
    const unsigned int blocks = (threads_needed + THREADS - 1u) / THREADS;

    taylor_flat_kernel<<<blocks, THREADS>>>(x, out, n_out);
}

// round 5
// speedup vs baseline: 1.9053x; 1.9053x over previous
#include <cuda_runtime.h>
#include <cstdint>

// TaylorExp via unified product formula.
// For row vector x[0..15], out[m] (m in 0..272):
//   p[0]=1, p[i]=2*s_quad*x[i-1]   (i=1..16)
//   q[0]=1, q[j]=x[j-1]/2          (j=1..16)
//   out[m] = p[t>>4] * q[(t&15) + (m>0)],  t = max(m-1,0)
// Check: m=0 -> 1*1 (handled as select); m=1..16 -> 1 * x[m-1]/2;
//        m=17+k -> 2*s_quad*x[k>>4] * x[k&15]/2 = s_quad*x_i*x_j.
//
// Warp handles 4 consecutive rows = 1092 floats = 4368B (16B-aligned group)
// -> all stores are aligned STG.128 (wavefront floor). Gathers from smem:
// per-row blocks of 40 floats: ps[17] at +0, qs_ext[19] at +17+(r&3).
// qs_ext[j] = x[j mod 16]/2 (3 wrap replicas). The (r&3) pad keeps every
// LDS.128 16B-aligned because lane start index m == -r (mod 4).

#define D 16
#define OPR 273
#define THREADS 256
#define ROWS_PER_BLOCK 32
#define ROW_STRIDE 40

__global__ __launch_bounds__(THREADS)
void taylor_pq_kernel(const float* __restrict__ x,
                      float* __restrict__ out,
                      int rows)
{
    const float s_quad  = 0.17677669529663689f;   // 1/(sqrt(2)*4)
    const float p_scale = 0.35355339059327378f;   // 2*s_quad

    __shared__ __align__(16) float sx[ROWS_PER_BLOCK * ROW_STRIDE];

    const int tid = threadIdx.x;
    const int block_row0 = blockIdx.x * ROWS_PER_BLOCK;

    if (block_row0 + ROWS_PER_BLOCK <= rows) {
        // ---- precompute p/q arrays (coalesced x load) ----
        #pragma unroll
        for (int h = 0; h < 2; ++h) {
            const int i  = tid + h * THREADS;        // 0..511
            const int rl = i >> 4;                   // local row 0..31
            const int j  = i & 15;
            const float v = x[(size_t)(block_row0 + rl) * D + j];
            const int rb   = rl * ROW_STRIDE;
            const int qoff = rb + 17 + (rl & 3);
            sx[rb + 1 + j] = v * p_scale;            // ps[1..16]
            sx[qoff + j]   = v * 0.5f;               // qs[0..15]
            if (j < 3) sx[qoff + 16 + j] = v * 0.5f; // wrap replicas qs[16..18]
            if (j == 0) sx[rb] = 1.0f;               // ps[0]
        }
        __syncthreads();

        const int warp = tid >> 5;
        const int lane = tid & 31;

        const float* sp = sx + warp * (4 * ROW_STRIDE); // ps of row r
        const float* sq = sp + 17;                      // qs_ext of row r

        float* ob = out + (size_t)(block_row0 + warp * 4) * OPR + lane * 4;

        int m = lane * 4;   // element index within current row (r starts at 0)

        #pragma unroll
        for (int s = 0; s < 9; ++s) {
            const bool act = (s < 8) || (lane < 17);  // last sweep: 17 lanes
            if (act) {
                // fast path — valid whenever all 4 elems are in row r, m>=1.
                // m==0 uses t0=3 (dummy, alignment-preserving); overridden below.
                const int t0 = (m == 0) ? 3 : (m - 1);
                const int a0 = t0 >> 4;
                const int b0 = t0 & 15;
                const float plo = sp[a0];
                const float phi = sp[a0 + 1];   // in-bounds garbage if a0==16; unused then
                const float4 q4 = *reinterpret_cast<const float4*>(sq + b0);
                float4 v;
                v.x = plo * q4.x;
                v.y = (b0 + 1 >= 16 ? phi : plo) * q4.y;
                v.z = (b0 + 2 >= 16 ? phi : plo) * q4.z;
                v.w = (b0 + 3 >= 16 ? phi : plo) * q4.w;

                if ((unsigned)(m - 1) >= 269u) {   // m==0 or row crossing (m>=270)
                    float vv[4];
                    #pragma unroll
                    for (int e = 0; e < 4; ++e) {
                        int me = m + e;
                        const float* spe = sp;
                        const float* sqe = sq;
                        if (me >= OPR) { me -= OPR; spe += ROW_STRIDE; sqe += ROW_STRIDE + 1; }
                        if (me == 0) {
                            vv[e] = 1.0f;
                        } else {
                            const int t = me - 1;
                            vv[e] = spe[t >> 4] * sqe[t & 15];
                        }
                    }
                    v.x = vv[0]; v.y = vv[1]; v.z = vv[2]; v.w = vv[3];
                }

                *reinterpret_cast<float4*>(ob + s * 128) = v;
            }
            // advance one sweep (128 elements); at most one row crossing
            m += 128;
            if (m >= OPR) { m -= OPR; sp += ROW_STRIDE; sq += ROW_STRIDE + 1; }
        }
    } else {
        // tail block (not hit for the bench shape): scalar fallback
        const unsigned int iend = (unsigned int)rows * OPR;
        for (unsigned int g = (unsigned int)block_row0 * OPR + tid; g < iend;
             g += THREADS) {
            const unsigned int row = g / OPR;
            const int mm = (int)(g - row * OPR);
            const float* xr = x + (size_t)row * D;
            float v;
            if (mm == 0) v = 1.0f;
            else if (mm < 17) v = xr[mm - 1] * 0.5f;
            else { const int k = mm - 17; v = xr[k >> 4] * xr[k & 15] * s_quad; }
            out[g] = v;
        }
    }
}

extern "C" void kernel_launch(void* const* d_in, const int* in_sizes, int n_in,
                              void* d_out, int out_size) {
    const float* x = (const float*)d_in[0];
    float* out = (float*)d_out;

    const int rows = in_sizes[0] / D;                    // 262144
    const int blocks = (rows + ROWS_PER_BLOCK - 1) / ROWS_PER_BLOCK;

    taylor_pq_kernel<<<blocks, THREADS>>>(x, out, rows);
}